// round 1
// baseline (speedup 1.0000x reference)
#include <cuda_runtime.h>
#include <math.h>

// Problem constants
#define B_      64
#define T_      256
#define DIM_    1024
#define ED_     512
#define NE_     8192
#define CODES_  64
#define NROWS_  4096            // B*CODES
#define K2_     4608            // ED*9
#define NSPLIT_ 8

// Output packing (concat of flattened outputs, float32):
// out [64,64,1024] | perplexity [1] | codebooks_used [8192] | min_indices [4096]
#define OFF_OUT   0
#define OFF_PERP  4194304
#define OFF_CB    4194305
#define OFF_IDX   4202497

// ---------------- scratch (static device globals; no allocation) ----------------
__device__ float g_Y[B_ * T_ * ED_];            // encoder-diff after projection [16384,512]
__device__ float g_Wc[K2_ * ED_];               // conv weights reordered [4608,512]
__device__ float g_col[NROWS_ * K2_];           // im2col of conv input [4096,4608]
__device__ float g_x[NROWS_ * ED_];             // encoder output diff x [4096,512]
__device__ float g_q[NROWS_ * ED_];             // quantized [4096,512]
__device__ float g_cnorm[NE_];                  // ||c||^2
__device__ unsigned long long g_part[NROWS_ * NSPLIT_];
__device__ int g_minidx[NROWS_];
__device__ int g_counts[NE_];

// ---------------- generic 128x128x8 SGEMM ----------------
// MODE 0: A = A0 - A1 (row-major, lda)   -> C = (last-first) @ W_in
// MODE 1: A = A0 (row-major, lda)        -> C = im2col @ Wc
// MODE 2: A = scrambled gather from quantized; epilogue adds bias
template <int MODE>
__global__ __launch_bounds__(256) void gemm128(
    const float* __restrict__ A0, const float* __restrict__ A1,
    const float* __restrict__ Bm, const float* __restrict__ bias,
    float* __restrict__ C, int M, int N, int K, int lda)
{
    __shared__ float As[8][128];
    __shared__ float Bs[8][128];

    const int tid  = threadIdx.x;
    const int tRow = tid >> 4;      // 0..15
    const int tCol = tid & 15;      // 0..15
    const int m0 = blockIdx.y * 128;
    const int n0 = blockIdx.x * 128;

    float acc[8][8];
#pragma unroll
    for (int i = 0; i < 8; ++i)
#pragma unroll
        for (int j = 0; j < 8; ++j) acc[i][j] = 0.f;

    for (int k0 = 0; k0 < K; k0 += 8) {
        // ---- load A tile (transposed into As[k][m]) ----
        if (MODE == 2) {
#pragma unroll
            for (int rep = 0; rep < 4; ++rep) {
                int e  = tid + rep * 256;
                int kk = e >> 7;
                int i  = e & 127;
                int m  = m0 + i;
                int k  = k0 + kk;
                int b  = m >> 6;
                int cc = m & 63;
                int p  = k >> 3;
                int eo = ((k & 7) << 6) + cc;
                As[kk][i] = A0[(size_t)((b << 6) + p) * ED_ + eo];
            }
        } else {
            int aRow = tid >> 1;
            int aCol = (tid & 1) << 2;
            const float4 v = *(const float4*)(A0 + (size_t)(m0 + aRow) * lda + k0 + aCol);
            float4 w = v;
            if (MODE == 0) {
                const float4 u = *(const float4*)(A1 + (size_t)(m0 + aRow) * lda + k0 + aCol);
                w.x = v.x - u.x; w.y = v.y - u.y; w.z = v.z - u.z; w.w = v.w - u.w;
            }
            As[aCol + 0][aRow] = w.x;
            As[aCol + 1][aRow] = w.y;
            As[aCol + 2][aRow] = w.z;
            As[aCol + 3][aRow] = w.w;
        }
        // ---- load B tile (row-major [K,N]) ----
        {
            int bRow = tid >> 5;
            int bCol = (tid & 31) << 2;
            const float4 bv = *(const float4*)(Bm + (size_t)(k0 + bRow) * N + n0 + bCol);
            *(float4*)(&Bs[bRow][bCol]) = bv;
        }
        __syncthreads();

#pragma unroll
        for (int kk = 0; kk < 8; ++kk) {
            float ra[8], rb[8];
#pragma unroll
            for (int i = 0; i < 8; ++i) ra[i] = As[kk][(tRow << 3) + i];
#pragma unroll
            for (int j = 0; j < 8; ++j) rb[j] = Bs[kk][(tCol << 3) + j];
#pragma unroll
            for (int i = 0; i < 8; ++i)
#pragma unroll
                for (int j = 0; j < 8; ++j) acc[i][j] = fmaf(ra[i], rb[j], acc[i][j]);
        }
        __syncthreads();
    }

    // ---- epilogue ----
#pragma unroll
    for (int i = 0; i < 8; ++i) {
        int m = m0 + (tRow << 3) + i;
        float* crow = C + (size_t)m * N + n0 + (tCol << 3);
        float4 v0, v1;
        if (MODE == 2) {
            const float* bp = bias + n0 + (tCol << 3);
            v0 = make_float4(acc[i][0] + bp[0], acc[i][1] + bp[1], acc[i][2] + bp[2], acc[i][3] + bp[3]);
            v1 = make_float4(acc[i][4] + bp[4], acc[i][5] + bp[5], acc[i][6] + bp[6], acc[i][7] + bp[7]);
        } else {
            v0 = make_float4(acc[i][0], acc[i][1], acc[i][2], acc[i][3]);
            v1 = make_float4(acc[i][4], acc[i][5], acc[i][6], acc[i][7]);
        }
        *(float4*)(crow)     = v0;
        *(float4*)(crow + 4) = v1;
    }
}

// ---------------- weight reorder conv_w [O,C,3,3] -> Wc [(c*9+k), O] ----------------
__global__ void reorder_w(const float* __restrict__ cw, float* __restrict__ wc)
{
    int e = blockIdx.x * 256 + threadIdx.x;
    if (e >= K2_ * ED_) return;
    int o  = e & 511;
    int ck = e >> 9;            // c*9 + k
    wc[e] = cw[(size_t)o * K2_ + ck];
}

// ---------------- im2col: g_Y [B,256,512] -> g_col [4096,4608] ----------------
__global__ void im2col_k(float* __restrict__ col)
{
    int e = blockIdx.x * 256 + threadIdx.x;
    if (e >= NROWS_ * K2_) return;
    int r  = e / K2_;
    int k2 = e - r * K2_;
    int c  = k2 / 9;
    int kk = k2 - c * 9;
    int ky = kk / 3;
    int kx = kk - ky * 3;
    int b = r >> 6, p = r & 63;
    int h = p >> 3, w = p & 7;
    int gy = 2 * h - 1 + ky;
    int gx = 2 * w - 1 + kx;
    float v = 0.f;
    if ((unsigned)gy < 16u && (unsigned)gx < 16u)
        v = g_Y[(size_t)(b * 256 + gy * 16 + gx) * ED_ + c];
    col[e] = v;
}

// ---------------- codebook norms ----------------
__global__ void cnorm_k(const float* __restrict__ Cb, float* __restrict__ cn)
{
    int row  = blockIdx.x * 8 + (threadIdx.x >> 5);
    int lane = threadIdx.x & 31;
    const float* p = Cb + (size_t)row * ED_;
    float s = 0.f;
    for (int i = lane; i < ED_; i += 32) { float v = p[i]; s = fmaf(v, v, s); }
#pragma unroll
    for (int off = 16; off > 0; off >>= 1) s += __shfl_down_sync(0xffffffffu, s, off);
    if (lane == 0) cn[row] = s;
}

// ---------------- distance GEMM + argmin epilogue ----------------
// score(n) = ||c_n||^2 - 2 x.c_n  (row-constant ||x||^2 dropped; argmin unchanged)
__global__ __launch_bounds__(256) void dist_argmin(
    const float* __restrict__ X, const float* __restrict__ Cb,
    const float* __restrict__ cn, unsigned long long* __restrict__ part)
{
    __shared__ float As[8][128];
    __shared__ float Bs[8][128];
    __shared__ unsigned long long sMin[128];

    const int tid  = threadIdx.x;
    const int tRow = tid >> 4;
    const int tCol = tid & 15;
    const int m0    = blockIdx.y * 128;
    const int split = blockIdx.x;

    if (tid < 128) sMin[tid] = ~0ull;
    __syncthreads();

    for (int nt = 0; nt < 8; ++nt) {
        const int n0 = split * 1024 + nt * 128;
        float acc[8][8];
#pragma unroll
        for (int i = 0; i < 8; ++i)
#pragma unroll
            for (int j = 0; j < 8; ++j) acc[i][j] = 0.f;

        for (int k0 = 0; k0 < ED_; k0 += 8) {
            int r  = tid >> 1;
            int c4 = (tid & 1) << 2;
            const float4 av = *(const float4*)(X + (size_t)(m0 + r) * ED_ + k0 + c4);
            As[c4 + 0][r] = av.x; As[c4 + 1][r] = av.y; As[c4 + 2][r] = av.z; As[c4 + 3][r] = av.w;
            const float4 bv = *(const float4*)(Cb + (size_t)(n0 + r) * ED_ + k0 + c4);
            Bs[c4 + 0][r] = bv.x; Bs[c4 + 1][r] = bv.y; Bs[c4 + 2][r] = bv.z; Bs[c4 + 3][r] = bv.w;
            __syncthreads();
#pragma unroll
            for (int kk = 0; kk < 8; ++kk) {
                float ra[8], rb[8];
#pragma unroll
                for (int i = 0; i < 8; ++i) ra[i] = As[kk][(tRow << 3) + i];
#pragma unroll
                for (int j = 0; j < 8; ++j) rb[j] = Bs[kk][(tCol << 3) + j];
#pragma unroll
                for (int i = 0; i < 8; ++i)
#pragma unroll
                    for (int j = 0; j < 8; ++j) acc[i][j] = fmaf(ra[i], rb[j], acc[i][j]);
            }
            __syncthreads();
        }

        // epilogue: per-thread local argmin over its 8 cols, then shared atomicMin
#pragma unroll
        for (int i = 0; i < 8; ++i) {
            float best = __int_as_float(0x7f800000);
            int bi = 0;
#pragma unroll
            for (int j = 0; j < 8; ++j) {
                int n = n0 + (tCol << 3) + j;
                float v = cn[n] - 2.f * acc[i][j];
                if (v < best) { best = v; bi = n; }
            }
            unsigned fu = __float_as_uint(best);
            fu = (fu & 0x80000000u) ? ~fu : (fu | 0x80000000u);  // monotone order map
            unsigned long long packed = ((unsigned long long)fu << 32) | (unsigned)bi;
            atomicMin(&sMin[(tRow << 3) + i], packed);
        }
        __syncthreads();
    }
    if (tid < 128) part[(size_t)(m0 + tid) * NSPLIT_ + split] = sMin[tid];
}

// ---------------- reduce partial argmins, histogram, write min_indices ----------------
__global__ void reduce_argmin(float* __restrict__ outIdxF, int writeIdx)
{
    int n = blockIdx.x * 256 + threadIdx.x;
    if (n >= NROWS_) return;
    unsigned long long best = ~0ull;
#pragma unroll
    for (int s = 0; s < NSPLIT_; ++s) {
        unsigned long long v = g_part[(size_t)n * NSPLIT_ + s];
        if (v < best) best = v;
    }
    int idx = (int)(unsigned)(best & 0xFFFFFFFFull);
    g_minidx[n] = idx;
    atomicAdd(&g_counts[idx], 1);
    if (writeIdx) outIdxF[n] = (float)idx;
}

// ---------------- noise substitution: quantized = x + (||x-hard||/||rand|| + eps)*rand ----------------
__global__ void noise_k(const float* __restrict__ Cb, const float* __restrict__ rv)
{
    const int n   = blockIdx.x;
    const int tid = threadIdx.x;      // 128 threads
    const int idx = g_minidx[n];
    const float* xr = g_x + (size_t)n * ED_;
    const float* hr = Cb + (size_t)idx * ED_;
    const float* rr = rv + (size_t)n * ED_;

    float s1 = 0.f, s2 = 0.f;
    for (int i = tid; i < ED_; i += 128) {
        float d = xr[i] - hr[i];
        s1 = fmaf(d, d, s1);
        float r = rr[i];
        s2 = fmaf(r, r, s2);
    }
#pragma unroll
    for (int off = 16; off > 0; off >>= 1) {
        s1 += __shfl_down_sync(0xffffffffu, s1, off);
        s2 += __shfl_down_sync(0xffffffffu, s2, off);
    }
    __shared__ float sh1[4], sh2[4];
    int wid = tid >> 5, lane = tid & 31;
    if (lane == 0) { sh1[wid] = s1; sh2[wid] = s2; }
    __syncthreads();
    float t1 = sh1[0] + sh1[1] + sh1[2] + sh1[3];
    float t2 = sh2[0] + sh2[1] + sh2[2] + sh2[3];
    float scale = sqrtf(t1) / sqrtf(t2) + 1e-12f;
    for (int i = tid; i < ED_; i += 128)
        g_q[(size_t)n * ED_ + i] = fmaf(scale, rr[i], xr[i]);
}

// ---------------- perplexity + codebooks_used ----------------
__global__ void stats_k(float* __restrict__ d_out, int out_size)
{
    __shared__ float red[256];
    int tid = threadIdx.x;
    float s = 0.f;
    for (int i = tid; i < NE_; i += 256) {
        float c = (float)g_counts[i];
        float p = c * (1.f / (float)NROWS_);
        s += p * logf(p + 1e-12f);
        if (out_size > OFF_CB + i) d_out[OFF_CB + i] = c;
    }
    red[tid] = s;
    __syncthreads();
    for (int st = 128; st > 0; st >>= 1) {
        if (tid < st) red[tid] += red[tid + st];
        __syncthreads();
    }
    if (tid == 0 && out_size > OFF_PERP) d_out[OFF_PERP] = expf(-red[0]);
}

// ---------------- host launcher ----------------
extern "C" void kernel_launch(void* const* d_in, const int* in_sizes, int n_in,
                              void* d_out, int out_size)
{
    const float* first = (const float*)d_in[0];
    const float* last  = (const float*)d_in[1];
    const float* W_in  = (const float*)d_in[2];
    // d_in[3] = b_in  : cancels in (last-first)
    const float* conv_w = (const float*)d_in[4];
    // d_in[5] = conv_b: cancels
    const float* W_out = (const float*)d_in[6];
    const float* b_out = (const float*)d_in[7];
    const float* codebooks = (const float*)d_in[8];
    const float* randv = (const float*)d_in[9];
    float* out = (float*)d_out;

    float *pY, *pWc, *pCol, *pX, *pQ, *pCn;
    unsigned long long* pPart;
    int *pCnt;
    cudaGetSymbolAddress((void**)&pY, g_Y);
    cudaGetSymbolAddress((void**)&pWc, g_Wc);
    cudaGetSymbolAddress((void**)&pCol, g_col);
    cudaGetSymbolAddress((void**)&pX, g_x);
    cudaGetSymbolAddress((void**)&pQ, g_q);
    cudaGetSymbolAddress((void**)&pCn, g_cnorm);
    cudaGetSymbolAddress((void**)&pPart, g_part);
    cudaGetSymbolAddress((void**)&pCnt, g_counts);

    cudaMemsetAsync(pCnt, 0, NE_ * sizeof(int));

    // 1. projection of the diff: [16384,1024]@[1024,512] -> g_Y
    gemm128<0><<<dim3(4, 128), 256>>>(last, first, W_in, nullptr, pY,
                                      B_ * T_, ED_, DIM_, DIM_);
    // 2. reorder conv weights (independent)
    reorder_w<<<(K2_ * ED_ + 255) / 256, 256>>>(conv_w, pWc);
    // 3. im2col of g_Y grid
    im2col_k<<<(NROWS_ * K2_ + 255) / 256, 256>>>(pCol);
    // 4. conv GEMM: [4096,4608]@[4608,512] -> g_x
    gemm128<1><<<dim3(4, 32), 256>>>(pCol, nullptr, pWc, nullptr, pX,
                                     NROWS_, ED_, K2_, K2_);
    // 5. codebook norms (independent)
    cnorm_k<<<NE_ / 8, 256>>>(codebooks, pCn);
    // 6. nearest codebook search
    dist_argmin<<<dim3(NSPLIT_, NROWS_ / 128), 256>>>(pX, codebooks, pCn, pPart);
    // 7. reduce + histogram + min_indices output
    int writeIdx = (out_size >= OFF_IDX + NROWS_) ? 1 : 0;
    reduce_argmin<<<NROWS_ / 256, 256>>>(out + OFF_IDX, writeIdx);
    // 8. noise substitution -> g_q
    noise_k<<<NROWS_, 128>>>(codebooks, randv);
    // 9. decode: scrambled-gather [4096,512]@[512,1024] + b_out -> out
    gemm128<2><<<dim3(8, 32), 256>>>(pQ, nullptr, W_out, b_out, out,
                                     NROWS_, DIM_, ED_, 0);
    // 10. perplexity + codebooks_used
    stats_k<<<1, 256>>>(out, out_size);
}

// round 5
// speedup vs baseline: 1.4773x; 1.4773x over previous
#include <cuda_runtime.h>
#include <math.h>
#include <stdint.h>

// ---------------- problem constants ----------------
#define DIM_    1024
#define ED_     512
#define NE_     8192
#define NROWS_  4096            // B*CODES
#define K2_     4608            // ED*9
#define NSPL_   64              // distance N-tiles (8192/128)

// Output packing (float32 concat):
// out [64,64,1024] | perplexity [1] | codebooks_used [8192] | min_indices [4096]
#define OFF_PERP  4194304
#define OFF_CB    4194305
#define OFF_IDX   4202497

// ---------------- scratch (static device globals) ----------------
__device__ float g_Y[16384 * ED_];                  // proj output [16384,512]
__device__ float g_col[(size_t)NROWS_ * K2_];       // im2col [4096,4608]
__device__ float g_x[NROWS_ * ED_];                 // encoder diff x [4096,512]
__device__ float g_Aq[NROWS_ * ED_];                // quantized, scrambled for decode
__device__ float g_WinT[ED_ * DIM_];                // W_in^T  [512,1024]
__device__ float g_WoutT[DIM_ * ED_];               // W_out^T [1024,512]
__device__ float g_cnorm[NE_];
__device__ unsigned long long g_part[NROWS_ * NSPL_];
__device__ int g_minidx[NROWS_];
__device__ int g_counts[NE_];

// ---------------- helpers ----------------
__device__ __forceinline__ uint32_t tf32_rna(float f) {
    uint32_t u; asm("cvt.rna.tf32.f32 %0, %1;" : "=r"(u) : "f"(f)); return u;
}
__device__ __forceinline__ void mma_tf32(float* c, const uint32_t* a, uint32_t b0, uint32_t b1) {
    asm volatile(
        "mma.sync.aligned.m16n8k8.row.col.f32.tf32.tf32.f32 "
        "{%0,%1,%2,%3}, {%4,%5,%6,%7}, {%8,%9}, {%0,%1,%2,%3};"
        : "+f"(c[0]), "+f"(c[1]), "+f"(c[2]), "+f"(c[3])
        : "r"(a[0]), "r"(a[1]), "r"(a[2]), "r"(a[3]), "r"(b0), "r"(b1));
}

// smem tile: 128 rows x 40 cols (pad 8) of u32
#define LDS_P   40
#define TILE_U  (128 * LDS_P)                 // u32 per tile
#define STAGE_U (4 * TILE_U)                  // Ahi, Alo, Bhi, Blo
#define SMEM_BYTES (2 * STAGE_U * 4 + 2048)   // 2 stages + argmin red area

// ---------------- 3xTF32 emulated-fp32 GEMM via mma.sync ----------------
// C[M,N] = A @ Bt^T; A [M,K] row-major, Bt [N,K] row-major. CTA tile 128x128, Kc=32.
// AMODE 0: A = A0 - A1.  EPI 0: store C.  EPI 1: store C + bias[n].  EPI 2: argmin(cn[n]-2*acc).
template <int AMODE, int EPI>
__global__ void __launch_bounds__(256, 1) mm_gemm(
    const float* __restrict__ A0, const float* __restrict__ A1,
    const float* __restrict__ Bt, const float* __restrict__ bias,
    const float* __restrict__ cn, float* __restrict__ C,
    unsigned long long* __restrict__ part,
    int K, int lda, int ldb, int ldc)
{
    extern __shared__ __align__(16) uint32_t smem[];
    const int tid  = threadIdx.x;
    const int wid  = tid >> 5;
    const int lane = tid & 31;
    const int g    = lane >> 2;     // 0..7
    const int t    = lane & 3;      // 0..3
    const int wm   = wid & 3;       // 4 warps along M (32 rows each)
    const int wn   = wid >> 2;      // 2 warps along N (64 cols each)
    const int m0   = blockIdx.y * 128;
    const int n0   = blockIdx.x * 128;

    float acc[2][8][4];
#pragma unroll
    for (int mf = 0; mf < 2; ++mf)
#pragma unroll
        for (int nf = 0; nf < 8; ++nf)
#pragma unroll
            for (int q = 0; q < 4; ++q) acc[mf][nf][q] = 0.f;

    const int NC = K >> 5;
    const int row_l = tid >> 3;          // 0..31? no: 256/8 = 32 -> need rows 0..127: e4 covers
    (void)row_l;

    float4 pa[4], pb[4];

    // global -> regs for chunk k0
    auto g2r = [&](int k0) {
#pragma unroll
        for (int i = 0; i < 4; ++i) {
            int e4 = tid + i * 256;          // 0..1023
            int row = e4 >> 3;               // 0..127
            int c4 = (e4 & 7) << 2;          // 0,4,..28
            pa[i] = *(const float4*)(A0 + (size_t)(m0 + row) * lda + k0 + c4);
            if (AMODE == 0) {
                const float4 u = *(const float4*)(A1 + (size_t)(m0 + row) * lda + k0 + c4);
                pa[i].x -= u.x; pa[i].y -= u.y; pa[i].z -= u.z; pa[i].w -= u.w;
            }
            pb[i] = *(const float4*)(Bt + (size_t)(n0 + row) * ldb + k0 + c4);
        }
    };
    // regs -> smem (split hi/lo)
    auto r2s = [&](int stage) {
        uint32_t* sAh = smem + stage * STAGE_U;
        uint32_t* sAl = sAh + TILE_U;
        uint32_t* sBh = sAl + TILE_U;
        uint32_t* sBl = sBh + TILE_U;
#pragma unroll
        for (int i = 0; i < 4; ++i) {
            int e4 = tid + i * 256;
            int row = e4 >> 3;
            int c4 = (e4 & 7) << 2;
            int off = row * LDS_P + c4;
            float v[4] = {pa[i].x, pa[i].y, pa[i].z, pa[i].w};
#pragma unroll
            for (int q = 0; q < 4; ++q) {
                uint32_t h = tf32_rna(v[q]);
                sAh[off + q] = h;
                sAl[off + q] = tf32_rna(v[q] - __uint_as_float(h));
            }
            float w[4] = {pb[i].x, pb[i].y, pb[i].z, pb[i].w};
#pragma unroll
            for (int q = 0; q < 4; ++q) {
                uint32_t h = tf32_rna(w[q]);
                sBh[off + q] = h;
                sBl[off + q] = tf32_rna(w[q] - __uint_as_float(h));
            }
        }
    };

    g2r(0);
    r2s(0);
    __syncthreads();

    for (int c = 0; c < NC; ++c) {
        const int st = c & 1;
        if (c + 1 < NC) g2r((c + 1) << 5);

        const uint32_t* sAh = smem + st * STAGE_U;
        const uint32_t* sAl = sAh + TILE_U;
        const uint32_t* sBh = sAl + TILE_U;
        const uint32_t* sBl = sBh + TILE_U;

#pragma unroll
        for (int ks = 0; ks < 4; ++ks) {
            const int kk = ks * 8 + t;
            uint32_t ah[2][4], al[2][4];
#pragma unroll
            for (int mf = 0; mf < 2; ++mf) {
                int m = wm * 32 + mf * 16 + g;
                ah[mf][0] = sAh[m * LDS_P + kk];
                ah[mf][1] = sAh[(m + 8) * LDS_P + kk];
                ah[mf][2] = sAh[m * LDS_P + kk + 4];
                ah[mf][3] = sAh[(m + 8) * LDS_P + kk + 4];
                al[mf][0] = sAl[m * LDS_P + kk];
                al[mf][1] = sAl[(m + 8) * LDS_P + kk];
                al[mf][2] = sAl[m * LDS_P + kk + 4];
                al[mf][3] = sAl[(m + 8) * LDS_P + kk + 4];
            }
#pragma unroll
            for (int nf = 0; nf < 8; ++nf) {
                int n = wn * 64 + nf * 8 + g;
                uint32_t bh0 = sBh[n * LDS_P + kk];
                uint32_t bh1 = sBh[n * LDS_P + kk + 4];
                uint32_t bl0 = sBl[n * LDS_P + kk];
                uint32_t bl1 = sBl[n * LDS_P + kk + 4];
#pragma unroll
                for (int mf = 0; mf < 2; ++mf) {
                    mma_tf32(acc[mf][nf], ah[mf], bh0, bh1);
                    mma_tf32(acc[mf][nf], ah[mf], bl0, bl1);
                    mma_tf32(acc[mf][nf], al[mf], bh0, bh1);
                }
            }
        }
        __syncthreads();
        if (c + 1 < NC) {
            r2s((c + 1) & 1);
            __syncthreads();
        }
    }

    // ---- epilogue ----
    // acc[mf][nf][q]: row = m0 + wm*32 + mf*16 + g + (q>=2 ? 8 : 0)
    //                 col = n0 + wn*64 + nf*8 + 2t + (q&1)
    if (EPI == 0 || EPI == 1) {
#pragma unroll
        for (int mf = 0; mf < 2; ++mf) {
#pragma unroll
            for (int half = 0; half < 2; ++half) {
                int row = m0 + wm * 32 + mf * 16 + g + half * 8;
                float* crow = C + (size_t)row * ldc + n0 + wn * 64;
#pragma unroll
                for (int nf = 0; nf < 8; ++nf) {
                    int colb = nf * 8 + 2 * t;
                    float2 v;
                    v.x = acc[mf][nf][half * 2 + 0];
                    v.y = acc[mf][nf][half * 2 + 1];
                    if (EPI == 1) {
                        v.x += bias[n0 + wn * 64 + colb];
                        v.y += bias[n0 + wn * 64 + colb + 1];
                    }
                    *(float2*)(crow + colb) = v;
                }
            }
        }
    } else {
        // argmin over this thread's 16 cols for each of its 4 row-instances
        unsigned long long* red = (unsigned long long*)(smem + 2 * STAGE_U); // [128][2]
#pragma unroll
        for (int mf = 0; mf < 2; ++mf) {
#pragma unroll
            for (int half = 0; half < 2; ++half) {
                float best = __int_as_float(0x7f800000);
                int bi = 0;
#pragma unroll
                for (int nf = 0; nf < 8; ++nf) {
#pragma unroll
                    for (int q = 0; q < 2; ++q) {
                        int n = n0 + wn * 64 + nf * 8 + 2 * t + q;
                        float v = cn[n] - 2.f * acc[mf][nf][half * 2 + q];
                        if (v < best) { best = v; bi = n; }
                    }
                }
                unsigned fu = __float_as_uint(best);
                fu = (fu & 0x80000000u) ? ~fu : (fu | 0x80000000u);
                unsigned long long packed = ((unsigned long long)fu << 32) | (unsigned)bi;
                // reduce across the 4 threads sharing this row (t = 0..3)
#pragma unroll
                for (int off = 1; off < 4; off <<= 1) {
                    unsigned long long o = __shfl_xor_sync(0xffffffffu, packed, off);
                    if (o < packed) packed = o;
                }
                if (t == 0) {
                    int rl = wm * 32 + mf * 16 + g + half * 8;   // 0..127
                    red[rl * 2 + wn] = packed;
                }
            }
        }
        __syncthreads();
        if (tid < 128) {
            unsigned long long a = red[tid * 2], b = red[tid * 2 + 1];
            part[(size_t)(m0 + tid) * NSPL_ + blockIdx.x] = (a < b) ? a : b;
        }
    }
}

// ---------------- small kernels ----------------
__global__ void transpose_k(const float* __restrict__ src, float* __restrict__ dst, int R, int C)
{
    int e = blockIdx.x * 256 + threadIdx.x;
    if (e >= R * C) return;
    int rr = e / C, cc = e - rr * C;
    dst[(size_t)cc * R + rr] = src[e];
}

__global__ void im2col_k(float* __restrict__ col)
{
    int e = blockIdx.x * 256 + threadIdx.x;
    if (e >= NROWS_ * K2_) return;
    int rr = e / K2_;
    int k2 = e - rr * K2_;
    int c = k2 / 9;
    int kk = k2 - c * 9;
    int ky = kk / 3;
    int kx = kk - ky * 3;
    int b = rr >> 6, p = rr & 63;
    int h = p >> 3, w = p & 7;
    int gy = 2 * h - 1 + ky;
    int gx = 2 * w - 1 + kx;
    float v = 0.f;
    if ((unsigned)gy < 16u && (unsigned)gx < 16u)
        v = g_Y[(size_t)(b * 256 + gy * 16 + gx) * ED_ + c];
    col[e] = v;
}

__global__ void cnorm_k(const float* __restrict__ Cb, float* __restrict__ cnp)
{
    int rr = blockIdx.x * 8 + (threadIdx.x >> 5);
    int lane = threadIdx.x & 31;
    const float* p = Cb + (size_t)rr * ED_;
    float s = 0.f;
    for (int i = lane; i < ED_; i += 32) { float v = p[i]; s = fmaf(v, v, s); }
#pragma unroll
    for (int off = 16; off > 0; off >>= 1) s += __shfl_down_sync(0xffffffffu, s, off);
    if (lane == 0) cnp[rr] = s;
}

__global__ void reduce_argmin(float* __restrict__ outIdxF, int writeIdx)
{
    int n = blockIdx.x * 256 + threadIdx.x;
    if (n >= NROWS_) return;
    unsigned long long best = ~0ull;
#pragma unroll 8
    for (int s = 0; s < NSPL_; ++s) {
        unsigned long long v = g_part[(size_t)n * NSPL_ + s];
        if (v < best) best = v;
    }
    int idx = (int)(unsigned)(best & 0xFFFFFFFFull);
    g_minidx[n] = idx;
    atomicAdd(&g_counts[idx], 1);
    if (writeIdx) outIdxF[n] = (float)idx;
}

// quantized = x + (||x-hard||/||rand|| + eps)*rand, written in decode-scrambled layout
__global__ void noise_k(const float* __restrict__ Cb, const float* __restrict__ rv)
{
    const int n = blockIdx.x;            // n = b*64 + p
    const int tid = threadIdx.x;         // 128 threads
    const int idx = g_minidx[n];
    const int b = n >> 6, p = n & 63;
    const float* xr = g_x + (size_t)n * ED_;
    const float* hr = Cb + (size_t)idx * ED_;
    const float* rr = rv + (size_t)n * ED_;

    float s1 = 0.f, s2 = 0.f;
    for (int i = tid; i < ED_; i += 128) {
        float d = xr[i] - hr[i];
        s1 = fmaf(d, d, s1);
        float rrr = rr[i];
        s2 = fmaf(rrr, rrr, s2);
    }
#pragma unroll
    for (int off = 16; off > 0; off >>= 1) {
        s1 += __shfl_down_sync(0xffffffffu, s1, off);
        s2 += __shfl_down_sync(0xffffffffu, s2, off);
    }
    __shared__ float sh1[4], sh2[4];
    int wid = tid >> 5, lane = tid & 31;
    if (lane == 0) { sh1[wid] = s1; sh2[wid] = s2; }
    __syncthreads();
    float t1 = sh1[0] + sh1[1] + sh1[2] + sh1[3];
    float t2 = sh2[0] + sh2[1] + sh2[2] + sh2[3];
    float scale = sqrtf(t1) / sqrtf(t2) + 1e-12f;
    for (int i = tid; i < ED_; i += 128) {
        float q = fmaf(scale, rr[i], xr[i]);
        // scrambled target: row m = b*64 + (i&63), col k = p*8 + (i>>6)
        g_Aq[(size_t)(b * 64 + (i & 63)) * ED_ + p * 8 + (i >> 6)] = q;
    }
}

__global__ void stats_k(float* __restrict__ d_out, int out_size)
{
    __shared__ float red[256];
    int tid = threadIdx.x;
    float s = 0.f;
    for (int i = tid; i < NE_; i += 256) {
        float c = (float)g_counts[i];
        float p = c * (1.f / (float)NROWS_);
        s += p * logf(p + 1e-12f);
        if (out_size > OFF_CB + i) d_out[OFF_CB + i] = c;
    }
    red[tid] = s;
    __syncthreads();
    for (int st = 128; st > 0; st >>= 1) {
        if (tid < st) red[tid] += red[tid + st];
        __syncthreads();
    }
    if (tid == 0 && out_size > OFF_PERP) d_out[OFF_PERP] = expf(-red[0]);
}

// ---------------- host launcher ----------------
extern "C" void kernel_launch(void* const* d_in, const int* in_sizes, int n_in,
                              void* d_out, int out_size)
{
    const float* first = (const float*)d_in[0];
    const float* last = (const float*)d_in[1];
    const float* W_in = (const float*)d_in[2];
    const float* conv_w = (const float*)d_in[4];   // [512, 4608] == [N,K] for conv GEMM
    const float* W_out = (const float*)d_in[6];
    const float* b_out = (const float*)d_in[7];
    const float* codebooks = (const float*)d_in[8];
    const float* randv = (const float*)d_in[9];
    float* out = (float*)d_out;

    float *pY, *pCol, *pX, *pAq, *pWinT, *pWoutT, *pCn;
    unsigned long long* pPart;
    int* pCnt;
    cudaGetSymbolAddress((void**)&pY, g_Y);
    cudaGetSymbolAddress((void**)&pCol, g_col);
    cudaGetSymbolAddress((void**)&pX, g_x);
    cudaGetSymbolAddress((void**)&pAq, g_Aq);
    cudaGetSymbolAddress((void**)&pWinT, g_WinT);
    cudaGetSymbolAddress((void**)&pWoutT, g_WoutT);
    cudaGetSymbolAddress((void**)&pCn, g_cnorm);
    cudaGetSymbolAddress((void**)&pPart, g_part);
    cudaGetSymbolAddress((void**)&pCnt, g_counts);

    cudaFuncSetAttribute(mm_gemm<0, 0>, cudaFuncAttributeMaxDynamicSharedMemorySize, SMEM_BYTES);
    cudaFuncSetAttribute(mm_gemm<1, 0>, cudaFuncAttributeMaxDynamicSharedMemorySize, SMEM_BYTES);
    cudaFuncSetAttribute(mm_gemm<1, 1>, cudaFuncAttributeMaxDynamicSharedMemorySize, SMEM_BYTES);
    cudaFuncSetAttribute(mm_gemm<1, 2>, cudaFuncAttributeMaxDynamicSharedMemorySize, SMEM_BYTES);

    cudaMemsetAsync(pCnt, 0, NE_ * sizeof(int));

    // weight transposes (to [N,K])
    transpose_k<<<(DIM_ * ED_ + 255) / 256, 256>>>(W_in, pWinT, DIM_, ED_);
    transpose_k<<<(ED_ * DIM_ + 255) / 256, 256>>>(W_out, pWoutT, ED_, DIM_);

    // 1. projection: (last-first)[16384,1024] @ W_in -> g_Y [16384,512]
    mm_gemm<0, 0><<<dim3(4, 128), 256, SMEM_BYTES>>>(
        last, first, pWinT, nullptr, nullptr, pY, nullptr, DIM_, DIM_, DIM_, ED_);
    // 2. im2col
    im2col_k<<<((size_t)NROWS_ * K2_ + 255) / 256, 256>>>(pCol);
    // 3. conv GEMM: col [4096,4608] @ conv_w^T -> g_x [4096,512]
    mm_gemm<1, 0><<<dim3(4, 32), 256, SMEM_BYTES>>>(
        pCol, nullptr, conv_w, nullptr, nullptr, pX, nullptr, K2_, K2_, K2_, ED_);
    // 4. codebook norms
    cnorm_k<<<NE_ / 8, 256>>>(codebooks, pCn);
    // 5. distance GEMM + fused argmin partials
    mm_gemm<1, 2><<<dim3(NSPL_, 32), 256, SMEM_BYTES>>>(
        pX, nullptr, codebooks, nullptr, pCn, nullptr, pPart, ED_, ED_, ED_, 0);
    // 6. reduce + histogram + min_indices
    int writeIdx = (out_size >= OFF_IDX + NROWS_) ? 1 : 0;
    reduce_argmin<<<NROWS_ / 256, 256>>>(out + OFF_IDX, writeIdx);
    // 7. noise substitution -> scrambled g_Aq
    noise_k<<<NROWS_, 128>>>(codebooks, randv);
    // 8. decode: g_Aq [4096,512] @ W_out + b_out -> out [4096,1024]
    mm_gemm<1, 1><<<dim3(8, 32), 256, SMEM_BYTES>>>(
        pAq, nullptr, pWoutT, b_out, nullptr, out, nullptr, ED_, ED_, ED_, DIM_);
    // 9. perplexity + codebooks_used
    stats_k<<<1, 256>>>(out, out_size);
}